// round 2
// baseline (speedup 1.0000x reference)
#include <cuda_runtime.h>
#include <cstdint>
#include <cstddef>

// ---------------------------------------------------------------------------
// RNN_fish: h_t = 0.8*h_{t-1} + (g.h_{t-1}) @ (0.2*wrec^T) + 0.2*x_{t-1}@wi + 0.005*n_{t-1}
// out_t = h_t @ wout  (out_0 = h0 @ wout broadcast)
//
// Round 1: single persistent kernel for the 511 sequential steps (software
// grid barrier) -> 5 graph nodes total, no graph-upload residual, no
// per-step launch overhead. fp32 FFMA2 math throughout.
// ---------------------------------------------------------------------------

namespace {
constexpr int Bn = 64;      // batch
constexpr int Sn = 512;     // seq len
constexpr int In = 128;     // input dim
constexpr int Hn = 2048;    // hidden
constexpr int On = 128;     // output dim
constexpr int KSPLIT = 8;
constexpr int KPER = Hn / KSPLIT;   // 256
constexpr int KC = 64;              // K chunk staged in smem
constexpr int NCTA = 128;           // persistent grid (<= 148 SMs, co-resident)
constexpr int NTHR = 512;
constexpr int HB = Hn * Bn;         // 131072
constexpr float kNoise = 0.005f;
constexpr float kAlpha = 0.2f;
}

// scratch (static device globals; allocation-free rule)
__device__ float g_h[(size_t)Sn * Hn * Bn];        // [t][k][b]
__device__ float g_W[(size_t)Hn * Hn];             // [k][j] = alpha*g[k]*wrec[j][k]
__device__ float g_U[(size_t)Sn * Hn * Bn];        // [t][j][b]  (t>=1)
__device__ float g_part[(size_t)KSPLIT * Hn * Bn]; // [q][j][b]
__device__ unsigned g_bar_count;
__device__ unsigned g_bar_gen;

// ---- packed f32x2 helpers (sm_103a) ----
__device__ __forceinline__ void ffma2(unsigned long long &acc, unsigned long long a,
                                      unsigned long long b) {
    asm("fma.rn.f32x2 %0, %1, %2, %0;" : "+l"(acc) : "l"(a), "l"(b));
}
__device__ __forceinline__ unsigned long long splat2(float w) {
    unsigned long long r;
    asm("mov.b64 %0, {%1, %1};" : "=l"(r) : "f"(w));
    return r;
}
__device__ __forceinline__ float2 unpack2(unsigned long long v) {
    float2 r;
    asm("mov.b64 {%0, %1}, %2;" : "=f"(r.x), "=f"(r.y) : "l"(v));
    return r;
}

// ---- software grid barrier (replay-deterministic: gen monotonic, count->0) ----
__device__ __forceinline__ void grid_sync_dev() {
    __syncthreads();
    if (threadIdx.x == 0) {
        __threadfence();
        unsigned old, my;
        asm volatile("ld.acquire.gpu.global.u32 %0, [%1];"
                     : "=r"(old) : "l"(&g_bar_gen) : "memory");
        asm volatile("atom.release.gpu.global.add.u32 %0, [%1], %2;"
                     : "=r"(my) : "l"(&g_bar_count), "r"(1u) : "memory");
        if (my == (unsigned)(NCTA - 1)) {
            asm volatile("st.global.u32 [%0], %1;" :: "l"(&g_bar_count), "r"(0u) : "memory");
            asm volatile("red.release.gpu.global.add.u32 [%0], %1;"
                         :: "l"(&g_bar_gen), "r"(1u) : "memory");
        } else {
            unsigned cur;
            do {
                asm volatile("ld.acquire.gpu.global.u32 %0, [%1];"
                             : "=r"(cur) : "l"(&g_bar_gen) : "memory");
            } while (cur == old);
        }
        __threadfence();
    }
    __syncthreads();
}

// ---------------------------------------------------------------------------
// W' prep: g_W[k][j] = alpha * g[k] * wrec[j][k]
// ---------------------------------------------------------------------------
__global__ __launch_bounds__(1024) void wprep_kernel(const float* __restrict__ wrec,
                                                     const float* __restrict__ g) {
    __shared__ float s[32][33];
    int tx = threadIdx.x, ty = threadIdx.y;
    int k0 = blockIdx.x * 32, j0 = blockIdx.y * 32;
    s[ty][tx] = wrec[(size_t)(j0 + ty) * Hn + k0 + tx];   // coalesced over k
    __syncthreads();
    int k = k0 + ty;
    g_W[(size_t)k * Hn + j0 + tx] = kAlpha * g[k] * s[tx][ty];  // coalesced over j
}

// ---------------------------------------------------------------------------
// h_0 init: g_h[0][k][b] = h0[k]
// ---------------------------------------------------------------------------
__global__ void hinit_kernel(const float* __restrict__ h0) {
    int n = blockIdx.x * blockDim.x + threadIdx.x;   // < Hn*Bn
    g_h[n] = h0[n >> 6];
}

// ---------------------------------------------------------------------------
// U[t][j][b] = alpha * sum_i x[b][t-1][i] * wi[i][j] + noise_std*noise[b][t-1][j]
// ---------------------------------------------------------------------------
__global__ __launch_bounds__(256) void u_kernel(const float* __restrict__ x,
                                                const float* __restrict__ noise,
                                                const float* __restrict__ wi) {
    __shared__ float As[64][66];   // [i][b]
    __shared__ float Ws[64][64];   // [i][j]
    int t = blockIdx.y + 1;
    int j0 = blockIdx.x * 64;
    int tid = threadIdx.x;
    int by = tid & 15, jx = tid >> 4;
    int b0 = by * 4;
    unsigned long long acc[4][2] = {};

    for (int i0 = 0; i0 < In; i0 += 64) {
        #pragma unroll
        for (int p = 0; p < 16; p++) {
            int f = tid + p * 256;
            int i = f & 63, b = f >> 6;
            As[i][b] = x[((size_t)b * Sn + (t - 1)) * In + i0 + i];
        }
        #pragma unroll
        for (int p = 0; p < 4; p++) {
            int f = tid + p * 256;
            int i = f >> 4, c = f & 15;
            *(float4*)&Ws[i][c * 4] = *(const float4*)&wi[(size_t)(i0 + i) * Hn + j0 + c * 4];
        }
        __syncthreads();
        #pragma unroll 16
        for (int k = 0; k < 64; k++) {
            const unsigned long long* ap = (const unsigned long long*)&As[k][b0];
            unsigned long long a01 = ap[0], a23 = ap[1];
            float4 w = *(const float4*)&Ws[k][jx * 4];
            unsigned long long w0 = splat2(w.x), w1 = splat2(w.y),
                               w2 = splat2(w.z), w3 = splat2(w.w);
            ffma2(acc[0][0], a01, w0); ffma2(acc[0][1], a23, w0);
            ffma2(acc[1][0], a01, w1); ffma2(acc[1][1], a23, w1);
            ffma2(acc[2][0], a01, w2); ffma2(acc[2][1], a23, w2);
            ffma2(acc[3][0], a01, w3); ffma2(acc[3][1], a23, w3);
        }
        __syncthreads();
    }
    #pragma unroll
    for (int jj = 0; jj < 4; jj++) {
        int j = j0 + jx * 4 + jj;
        float2 lo = unpack2(acc[jj][0]), hi = unpack2(acc[jj][1]);
        float4 v;
        v.x = kAlpha * lo.x + kNoise * noise[((size_t)(b0 + 0) * Sn + (t - 1)) * Hn + j];
        v.y = kAlpha * lo.y + kNoise * noise[((size_t)(b0 + 1) * Sn + (t - 1)) * Hn + j];
        v.z = kAlpha * hi.x + kNoise * noise[((size_t)(b0 + 2) * Sn + (t - 1)) * Hn + j];
        v.w = kAlpha * hi.y + kNoise * noise[((size_t)(b0 + 3) * Sn + (t - 1)) * Hn + j];
        *(float4*)&g_U[((size_t)t * Hn + j) * Bn + b0] = v;
    }
}

// ---------------------------------------------------------------------------
// Persistent sequential loop: 511 steps, two phases per step.
//   phase 1: g_part[kq][j][b] = sum_{k in slice} h_{t-1}[k][b] * W'[k][j]
//            CTA = (jt 0..15 -> 128 j, kq 0..7 -> 256 k), 512 thr, 4x4/thread
//   phase 2: h_t = 0.8*h_{t-1} + sum_q part[q] + U[t]
// ---------------------------------------------------------------------------
__global__ __launch_bounds__(NTHR, 1) void loop_kernel() {
    __shared__ float As[KC][Bn];     // 16 KB
    __shared__ float Ws[KC][128];    // 32 KB
    int cta = blockIdx.x, tid = threadIdx.x;
    int jt = cta >> 3, kq = cta & 7;
    int j0 = jt * 128, kbase = kq * KPER;
    int by = tid & 15, jx = tid >> 4;     // jx 0..31
    int b0 = by * 4;
    int gt = cta * NTHR + tid;            // phase-2 base index

    for (int t = 1; t < Sn; t++) {
        const float* hprev = g_h + (size_t)(t - 1) * HB;
        unsigned long long acc[4][2] = {};

        for (int kc = 0; kc < KPER; kc += KC) {
            const float4* asrc = (const float4*)(hprev + (size_t)(kbase + kc) * Bn);
            float4* adst = (float4*)&As[0][0];
            adst[tid]       = __ldcg(&asrc[tid]);
            adst[tid + 512] = __ldcg(&asrc[tid + 512]);
            #pragma unroll
            for (int p = 0; p < 4; p++) {
                int f = tid + p * 512;              // < 2048 float4
                int k = f >> 5, c = f & 31;
                *(float4*)&Ws[k][c * 4] =
                    *(const float4*)&g_W[(size_t)(kbase + kc + k) * Hn + j0 + c * 4];
            }
            __syncthreads();
            #pragma unroll 16
            for (int k = 0; k < KC; k++) {
                const unsigned long long* ap = (const unsigned long long*)&As[k][b0];
                unsigned long long a01 = ap[0], a23 = ap[1];
                float4 w = *(const float4*)&Ws[k][jx * 4];
                unsigned long long w0 = splat2(w.x), w1 = splat2(w.y),
                                   w2 = splat2(w.z), w3 = splat2(w.w);
                ffma2(acc[0][0], a01, w0); ffma2(acc[0][1], a23, w0);
                ffma2(acc[1][0], a01, w1); ffma2(acc[1][1], a23, w1);
                ffma2(acc[2][0], a01, w2); ffma2(acc[2][1], a23, w2);
                ffma2(acc[3][0], a01, w3); ffma2(acc[3][1], a23, w3);
            }
            __syncthreads();
        }
        float* pout = g_part + ((size_t)kq * Hn + j0 + jx * 4) * Bn + b0;
        #pragma unroll
        for (int jj = 0; jj < 4; jj++) {
            float2 lo = unpack2(acc[jj][0]), hi = unpack2(acc[jj][1]);
            __stcg((float4*)(pout + (size_t)jj * Bn),
                   make_float4(lo.x, lo.y, hi.x, hi.y));
        }

        grid_sync_dev();

        // phase 2: 65536 threads x 2 elems
        #pragma unroll
        for (int r = 0; r < 2; r++) {
            int n = gt + r * (NCTA * NTHR);
            float s = 0.f;
            #pragma unroll
            for (int q = 0; q < KSPLIT; q++) s += __ldcg(&g_part[(size_t)q * HB + n]);
            float hp = __ldcg(&g_h[(size_t)(t - 1) * HB + n]);
            g_h[(size_t)t * HB + n] = (1.f - kAlpha) * hp + s + g_U[(size_t)t * HB + n];
        }

        grid_sync_dev();
    }
}

// ---------------------------------------------------------------------------
// out[b][t][o] = sum_k g_h[t][k][b] * wout[k][o]  -- one block per t
// ---------------------------------------------------------------------------
__global__ __launch_bounds__(256) void out_kernel(const float* __restrict__ wout,
                                                  float* __restrict__ out) {
    __shared__ float As[32][Bn];
    __shared__ float Ws[32][On];
    int t = blockIdx.x;
    int tid = threadIdx.x;
    int ox = tid & 31, by = tid >> 5;
    int o0 = ox * 4, b0 = by * 8;
    unsigned long long acc[4][4] = {};

    const float* hsrc = g_h + (size_t)t * HB;
    for (int k0 = 0; k0 < Hn; k0 += 32) {
        const float4* asrc = (const float4*)(hsrc + (size_t)k0 * Bn);
        float4* adst = (float4*)&As[0][0];
        #pragma unroll
        for (int p = 0; p < 2; p++) adst[tid + p * 256] = asrc[tid + p * 256];
        #pragma unroll
        for (int p = 0; p < 4; p++) {
            int f = tid + p * 256;
            int k = f >> 5, c = f & 31;
            *(float4*)&Ws[k][c * 4] = *(const float4*)&wout[(size_t)(k0 + k) * On + c * 4];
        }
        __syncthreads();
        #pragma unroll 8
        for (int k = 0; k < 32; k++) {
            const unsigned long long* ap = (const unsigned long long*)&As[k][b0];
            unsigned long long a01 = ap[0], a23 = ap[1], a45 = ap[2], a67 = ap[3];
            float4 w = *(const float4*)&Ws[k][o0];
            unsigned long long w0 = splat2(w.x), w1 = splat2(w.y),
                               w2 = splat2(w.z), w3 = splat2(w.w);
            ffma2(acc[0][0], a01, w0); ffma2(acc[0][1], a01, w1);
            ffma2(acc[0][2], a01, w2); ffma2(acc[0][3], a01, w3);
            ffma2(acc[1][0], a23, w0); ffma2(acc[1][1], a23, w1);
            ffma2(acc[1][2], a23, w2); ffma2(acc[1][3], a23, w3);
            ffma2(acc[2][0], a45, w0); ffma2(acc[2][1], a45, w1);
            ffma2(acc[2][2], a45, w2); ffma2(acc[2][3], a45, w3);
            ffma2(acc[3][0], a67, w0); ffma2(acc[3][1], a67, w1);
            ffma2(acc[3][2], a67, w2); ffma2(acc[3][3], a67, w3);
        }
        __syncthreads();
    }
    #pragma unroll
    for (int bp = 0; bp < 4; bp++) {
        float2 u0 = unpack2(acc[bp][0]), u1 = unpack2(acc[bp][1]);
        float2 u2 = unpack2(acc[bp][2]), u3 = unpack2(acc[bp][3]);
        int b = b0 + bp * 2;
        *(float4*)&out[((size_t)b * Sn + t) * On + o0] = make_float4(u0.x, u1.x, u2.x, u3.x);
        *(float4*)&out[((size_t)(b + 1) * Sn + t) * On + o0] =
            make_float4(u0.y, u1.y, u2.y, u3.y);
    }
}

// ---------------------------------------------------------------------------
extern "C" void kernel_launch(void* const* d_in, const int* in_sizes, int n_in,
                              void* d_out, int out_size) {
    const float* x     = (const float*)d_in[0];   // (64,512,128)
    const float* noise = (const float*)d_in[1];   // (64,512,2048)
    const float* wi    = (const float*)d_in[2];   // (128,2048)
    const float* wrec  = (const float*)d_in[3];   // (2048,2048)
    const float* wout  = (const float*)d_in[4];   // (2048,128)
    const float* g     = (const float*)d_in[5];   // (2048,1)
    const float* h0    = (const float*)d_in[6];   // (2048,)
    float* out = (float*)d_out;                   // (64,512,128)

    wprep_kernel<<<dim3(Hn / 32, Hn / 32), dim3(32, 32)>>>(wrec, g);
    u_kernel<<<dim3(Hn / 64, Sn - 1), 256>>>(x, noise, wi);
    hinit_kernel<<<Hn * Bn / 256, 256>>>(h0);
    loop_kernel<<<NCTA, NTHR>>>();
    out_kernel<<<Sn, 256>>>(wout, out);
}

// round 6
// speedup vs baseline: 1.5751x; 1.5751x over previous
#include <cuda_runtime.h>
#include <cuda_bf16.h>
#include <cstdint>
#include <cstddef>

// ---------------------------------------------------------------------------
// RNN_fish, persistent kernel with warp-level bf16 mma.sync (HMMA):
//   h_t = 0.8*h_{t-1} + (g.h_{t-1}) @ (0.2*wrec^T) + U_t
// W' and h kept as bf16 hi+lo pairs; 3 mma chains accumulate in fp32.
// (tcgen05 is unavailable: harness compiles at plain sm_103, no 'a' features.)
// ---------------------------------------------------------------------------

namespace {
constexpr int Bn = 64;
constexpr int Sn = 512;
constexpr int In = 128;
constexpr int Hn = 2048;
constexpr int On = 128;
constexpr int KSPLIT = 8;
constexpr int KPER = Hn / KSPLIT;     // 256 k per CTA
constexpr int NCTA = 128;             // 16 j-tiles x 8 k-slices
constexpr int NTHR = 512;             // 16 warps
constexpr int HB = Hn * Bn;
constexpr float kNoise = 0.005f;
constexpr float kAlpha = 0.2f;

// smem layout (bytes). W rows padded to 528B (264 bf16) -> conflict-free ldmatrix.
constexpr int ROWB = 528;
constexpr int OFF_WH = 0;                       // 128*528 = 67584
constexpr int OFF_WL = OFF_WH + 128 * ROWB;     // 67584
constexpr int OFF_BH = OFF_WL + 128 * ROWB;     // 135168 (64*528 = 33792)
constexpr int OFF_BL = OFF_BH + 64 * ROWB;      // 168960
constexpr int OFF_RED = OFF_BH;                 // pair-reduce stage, 8*1280*4 = 40960
constexpr int OFF_STG = OFF_RED + 40960;        // 176128 (+16*66*4 = 4224)
constexpr int SMEM_TOTAL = OFF_BL + 64 * ROWB;  // 202752
}

// device globals (allocation-free rule)
__device__ float g_h[(size_t)Sn * Hn * Bn];          // [t][j][b]
__device__ float g_U[(size_t)Sn * Hn * Bn];          // [t][j][b] (t>=1)
__device__ float g_part[(size_t)KSPLIT * Hn * Bn];   // [q][j][b]
__device__ __nv_bfloat16 g_Wh[(size_t)Hn * Hn];      // [j][k] hi of 0.2*g[k]*wrec[j][k]
__device__ __nv_bfloat16 g_Wl[(size_t)Hn * Hn];      // [j][k] lo
__device__ __nv_bfloat16 g_hbH[(size_t)Bn * Hn];     // [b][k] hi of h_{t-1}
__device__ __nv_bfloat16 g_hbL[(size_t)Bn * Hn];     // [b][k] lo
__device__ unsigned g_bar_count;
__device__ unsigned g_bar_gen;

// ---- helpers ----
__device__ __forceinline__ uint32_t smem_u32(const void* p) {
    uint32_t a;
    asm("{ .reg .u64 t; cvta.to.shared.u64 t, %1; cvt.u32.u64 %0, t; }" : "=r"(a) : "l"(p));
    return a;
}
__device__ __forceinline__ void ldsm4(uint32_t a[4], uint32_t addr) {
    asm volatile("ldmatrix.sync.aligned.m8n8.x4.shared.b16 {%0,%1,%2,%3}, [%4];"
                 : "=r"(a[0]), "=r"(a[1]), "=r"(a[2]), "=r"(a[3]) : "r"(addr));
}
__device__ __forceinline__ void mma16816(float c[4], const uint32_t a[4],
                                         uint32_t b0, uint32_t b1) {
    asm volatile("mma.sync.aligned.m16n8k16.row.col.f32.bf16.bf16.f32 "
                 "{%0,%1,%2,%3}, {%4,%5,%6,%7}, {%8,%9}, {%0,%1,%2,%3};"
                 : "+f"(c[0]), "+f"(c[1]), "+f"(c[2]), "+f"(c[3])
                 : "r"(a[0]), "r"(a[1]), "r"(a[2]), "r"(a[3]), "r"(b0), "r"(b1));
}
__device__ __forceinline__ void ffma2(unsigned long long &acc, unsigned long long a,
                                      unsigned long long b) {
    asm("fma.rn.f32x2 %0, %1, %2, %0;" : "+l"(acc) : "l"(a), "l"(b));
}
__device__ __forceinline__ unsigned long long splat2(float w) {
    unsigned long long r;
    asm("mov.b64 %0, {%1, %1};" : "=l"(r) : "f"(w));
    return r;
}
__device__ __forceinline__ float2 unpack2(unsigned long long v) {
    float2 r;
    asm("mov.b64 {%0, %1}, %2;" : "=f"(r.x), "=f"(r.y) : "l"(v));
    return r;
}

// software grid barrier (replay-deterministic)
__device__ __forceinline__ void grid_sync_dev() {
    __syncthreads();
    if (threadIdx.x == 0) {
        __threadfence();
        unsigned old, my;
        asm volatile("ld.acquire.gpu.global.u32 %0, [%1];"
                     : "=r"(old) : "l"(&g_bar_gen) : "memory");
        asm volatile("atom.release.gpu.global.add.u32 %0, [%1], %2;"
                     : "=r"(my) : "l"(&g_bar_count), "r"(1u) : "memory");
        if (my == (unsigned)(NCTA - 1)) {
            asm volatile("st.global.u32 [%0], %1;" :: "l"(&g_bar_count), "r"(0u) : "memory");
            asm volatile("red.release.gpu.global.add.u32 [%0], %1;"
                         :: "l"(&g_bar_gen), "r"(1u) : "memory");
        } else {
            unsigned cur;
            do {
                asm volatile("ld.acquire.gpu.global.u32 %0, [%1];"
                             : "=r"(cur) : "l"(&g_bar_gen) : "memory");
            } while (cur == old);
        }
        __threadfence();
    }
    __syncthreads();
}

// ---------------------------------------------------------------------------
// prep kernels
// ---------------------------------------------------------------------------
__global__ void wprep_kernel(const float* __restrict__ wrec, const float* __restrict__ g) {
    int n = blockIdx.x * blockDim.x + threadIdx.x;      // < Hn*Hn  ([j][k])
    int k = n & (Hn - 1);
    float v = kAlpha * g[k] * wrec[n];
    __nv_bfloat16 hi = __float2bfloat16(v);
    g_Wh[n] = hi;
    g_Wl[n] = __float2bfloat16(v - __bfloat162float(hi));
}

__global__ void hinit_kernel(const float* __restrict__ h0) {
    int n = blockIdx.x * blockDim.x + threadIdx.x;      // < Hn*Bn, [j][b]
    g_h[n] = h0[n >> 6];
}

__global__ void hbinit_kernel(const float* __restrict__ h0) {
    int n = blockIdx.x * blockDim.x + threadIdx.x;      // < Bn*Hn, [b][k]
    float v = h0[n & (Hn - 1)];
    __nv_bfloat16 hi = __float2bfloat16(v);
    g_hbH[n] = hi;
    g_hbL[n] = __float2bfloat16(v - __bfloat162float(hi));
}

// ---------------------------------------------------------------------------
// U[t][j][b] = alpha * x[b][t-1]@wi[:,j] + noise_std*noise[b][t-1][j]
// ---------------------------------------------------------------------------
__global__ __launch_bounds__(256) void u_kernel(const float* __restrict__ x,
                                                const float* __restrict__ noise,
                                                const float* __restrict__ wi) {
    __shared__ float As[64][66];
    __shared__ float Ws[64][64];
    int t = blockIdx.y + 1;
    int j0 = blockIdx.x * 64;
    int tid = threadIdx.x;
    int by = tid & 15, jx = tid >> 4;
    int b0 = by * 4;
    unsigned long long acc[4][2] = {};

    for (int i0 = 0; i0 < In; i0 += 64) {
        #pragma unroll
        for (int p = 0; p < 16; p++) {
            int f = tid + p * 256;
            int i = f & 63, b = f >> 6;
            As[i][b] = x[((size_t)b * Sn + (t - 1)) * In + i0 + i];
        }
        #pragma unroll
        for (int p = 0; p < 4; p++) {
            int f = tid + p * 256;
            int i = f >> 4, c = f & 15;
            *(float4*)&Ws[i][c * 4] = *(const float4*)&wi[(size_t)(i0 + i) * Hn + j0 + c * 4];
        }
        __syncthreads();
        #pragma unroll 16
        for (int k = 0; k < 64; k++) {
            const unsigned long long* ap = (const unsigned long long*)&As[k][b0];
            unsigned long long a01 = ap[0], a23 = ap[1];
            float4 w = *(const float4*)&Ws[k][jx * 4];
            unsigned long long w0 = splat2(w.x), w1 = splat2(w.y),
                               w2 = splat2(w.z), w3 = splat2(w.w);
            ffma2(acc[0][0], a01, w0); ffma2(acc[0][1], a23, w0);
            ffma2(acc[1][0], a01, w1); ffma2(acc[1][1], a23, w1);
            ffma2(acc[2][0], a01, w2); ffma2(acc[2][1], a23, w2);
            ffma2(acc[3][0], a01, w3); ffma2(acc[3][1], a23, w3);
        }
        __syncthreads();
    }
    #pragma unroll
    for (int jj = 0; jj < 4; jj++) {
        int j = j0 + jx * 4 + jj;
        float2 lo = unpack2(acc[jj][0]), hi = unpack2(acc[jj][1]);
        float4 v;
        v.x = kAlpha * lo.x + kNoise * noise[((size_t)(b0 + 0) * Sn + (t - 1)) * Hn + j];
        v.y = kAlpha * lo.y + kNoise * noise[((size_t)(b0 + 1) * Sn + (t - 1)) * Hn + j];
        v.z = kAlpha * hi.x + kNoise * noise[((size_t)(b0 + 2) * Sn + (t - 1)) * Hn + j];
        v.w = kAlpha * hi.y + kNoise * noise[((size_t)(b0 + 3) * Sn + (t - 1)) * Hn + j];
        *(float4*)&g_U[((size_t)t * Hn + j) * Bn + b0] = v;
    }
}

// ---------------------------------------------------------------------------
// persistent HMMA loop. CTA (jt,kq): partial D[128j x 64b] over its 256-k slice.
// 16 warps: tile = wid>>1, khalf = wid&1; warp tile 32j x 32b, K=128 per warp.
// 3 bf16 chains (Whi*hhi + Wlo*hhi + Whi*hlo), fp32 accumulate.
// pair (wid, wid^1) reduces k-halves via SMEM, writes g_part[kq].
// ---------------------------------------------------------------------------
__global__ __launch_bounds__(NTHR, 1) void loop_kernel() {
    extern __shared__ char smem[];
    const uint32_t sb = smem_u32(smem);
    const int tid = threadIdx.x;
    const int wid = tid >> 5, lane = tid & 31;
    const int cta = blockIdx.x;
    const int jt = cta >> 3, kq = cta & 7;
    const int j0 = jt * 128;
    const int kbase = kq * KPER;
    const int rc = cta * 16;               // phase-2 j-base

    const int tile = wid >> 1;             // 0..7
    const int khalf = wid & 1;
    const int mg = tile >> 1;              // 0..3 (32 j each)
    const int nh = tile & 1;               // 0..1 (32 b each)

    // ---- prologue: resident W hi/lo -> SMEM (padded rows) ----
    #pragma unroll
    for (int p = 0; p < 8; p++) {
        int f = tid + p * 512;             // < 4096
        int r = f >> 5, c = f & 31;
        size_t gi = (size_t)(j0 + r) * Hn + kbase + c * 8;
        *(uint4*)(smem + OFF_WH + r * ROWB + c * 16) = *(const uint4*)&g_Wh[gi];
        *(uint4*)(smem + OFF_WL + r * ROWB + c * 16) = *(const uint4*)&g_Wl[gi];
    }
    __syncthreads();

    // per-lane ldmatrix addresses (byte offsets within W/B blocks)
    const uint32_t aLane =
        (uint32_t)(mg * 32 + (lane & 15)) * ROWB + khalf * 256 + (lane >> 4) * 16;
    const uint32_t bLane =
        (uint32_t)(nh * 32 + (lane & 7) + ((lane >> 4) & 1) * 8) * ROWB +
        khalf * 256 + ((lane >> 3) & 1) * 16;
    const int g8 = lane >> 2, tg = lane & 3;
    float* red = (float*)(smem + OFF_RED) + tile * 1280;   // 32 rows x 40 floats
    float (*stage)[66] = (float (*)[66])(smem + OFF_STG);

    for (int t = 1; t < Sn; t++) {
        // ---- load B (h hi/lo slice) ----
        #pragma unroll
        for (int p = 0; p < 4; p++) {
            int f = tid + p * 512;         // < 2048
            int b = f >> 5, c = f & 31;
            size_t gi = (size_t)b * Hn + kbase + c * 8;
            uint4 vh = __ldcg((const uint4*)&g_hbH[gi]);
            *(uint4*)(smem + OFF_BH + b * ROWB + c * 16) = vh;
            uint4 vl = __ldcg((const uint4*)&g_hbL[gi]);
            *(uint4*)(smem + OFF_BL + b * ROWB + c * 16) = vl;
        }
        __syncthreads();

        // ---- 3 mma chains ----
        float acc[2][4][4] = {};
        #pragma unroll
        for (int ch = 0; ch < 3; ch++) {
            const uint32_t aBase = sb + (ch == 1 ? OFF_WL : OFF_WH) + aLane;
            const uint32_t bBase = sb + (ch == 2 ? OFF_BL : OFF_BH) + bLane;
            #pragma unroll
            for (int kk = 0; kk < 8; kk++) {
                uint32_t A0[4], A1[4], Bv[4], Bw[4];
                ldsm4(A0, aBase + kk * 32);
                ldsm4(A1, aBase + kk * 32 + 16 * ROWB);
                ldsm4(Bv, bBase + kk * 32);
                ldsm4(Bw, bBase + kk * 32 + 16 * ROWB);
                mma16816(acc[0][0], A0, Bv[0], Bv[1]);
                mma16816(acc[0][1], A0, Bv[2], Bv[3]);
                mma16816(acc[0][2], A0, Bw[0], Bw[1]);
                mma16816(acc[0][3], A0, Bw[2], Bw[3]);
                mma16816(acc[1][0], A1, Bv[0], Bv[1]);
                mma16816(acc[1][1], A1, Bv[2], Bv[3]);
                mma16816(acc[1][2], A1, Bw[0], Bw[1]);
                mma16816(acc[1][3], A1, Bw[2], Bw[3]);
            }
        }
        __syncthreads();   // all warps done reading B (red overlays BH)

        // ---- pair-reduce k halves, write g_part ----
        if (khalf) {
            #pragma unroll
            for (int mt = 0; mt < 2; mt++)
                #pragma unroll
                for (int nt = 0; nt < 4; nt++) {
                    int r0 = mt * 16 + g8, cc = nt * 8 + tg * 2;
                    *(float2*)&red[r0 * 40 + cc] =
                        make_float2(acc[mt][nt][0], acc[mt][nt][1]);
                    *(float2*)&red[(r0 + 8) * 40 + cc] =
                        make_float2(acc[mt][nt][2], acc[mt][nt][3]);
                }
        }
        __syncthreads();
        if (!khalf) {
            #pragma unroll
            for (int mt = 0; mt < 2; mt++)
                #pragma unroll
                for (int nt = 0; nt < 4; nt++) {
                    int r0 = mt * 16 + g8, cc = nt * 8 + tg * 2;
                    float2 p0 = *(float2*)&red[r0 * 40 + cc];
                    float2 p1 = *(float2*)&red[(r0 + 8) * 40 + cc];
                    int j = j0 + mg * 32 + r0;
                    int bc = nh * 32 + cc;
                    __stcg((float2*)&g_part[((size_t)kq * Hn + j) * Bn + bc],
                           make_float2(acc[mt][nt][0] + p0.x, acc[mt][nt][1] + p0.y));
                    __stcg((float2*)&g_part[((size_t)kq * Hn + j + 8) * Bn + bc],
                           make_float2(acc[mt][nt][2] + p1.x, acc[mt][nt][3] + p1.y));
                }
        }

        grid_sync_dev();

        // ---- phase 2: reduce 8 k-slices + leak + U; CTA owns j in [rc, rc+16) ----
        {
            int e = tid * 2;
            int jl = e >> 6, bb = e & 63;
            size_t idx = (size_t)(rc + jl) * Bn + bb;
            float2 s = make_float2(0.f, 0.f);
            #pragma unroll
            for (int q = 0; q < KSPLIT; q++) {
                float2 v = __ldcg((const float2*)&g_part[(size_t)q * HB + idx]);
                s.x += v.x; s.y += v.y;
            }
            float2 hp = *(const float2*)&g_h[(size_t)(t - 1) * HB + idx];
            float2 uu = *(const float2*)&g_U[(size_t)t * HB + idx];
            float2 hn = make_float2((1.f - kAlpha) * hp.x + s.x + uu.x,
                                    (1.f - kAlpha) * hp.y + s.y + uu.y);
            *(float2*)&g_h[(size_t)t * HB + idx] = hn;
            *(float2*)&stage[jl][bb] = hn;
        }
        __syncthreads();
        {
            int b = tid >> 3, kk = tid & 7;
            float x0 = stage[kk * 2][b];
            float x1 = stage[kk * 2 + 1][b];
            __nv_bfloat16 h0b = __float2bfloat16(x0);
            __nv_bfloat16 h1b = __float2bfloat16(x1);
            __nv_bfloat16 l0b = __float2bfloat16(x0 - __bfloat162float(h0b));
            __nv_bfloat16 l1b = __float2bfloat16(x1 - __bfloat162float(h1b));
            __nv_bfloat162 hv; hv.x = h0b; hv.y = h1b;
            __nv_bfloat162 lv; lv.x = l0b; lv.y = l1b;
            *(__nv_bfloat162*)&g_hbH[(size_t)b * Hn + rc + kk * 2] = hv;
            *(__nv_bfloat162*)&g_hbL[(size_t)b * Hn + rc + kk * 2] = lv;
        }

        grid_sync_dev();
    }
}

// ---------------------------------------------------------------------------
// out[b][t][o] = sum_k g_h[t][k][b] * wout[k][o]
// ---------------------------------------------------------------------------
__global__ __launch_bounds__(256) void out_kernel(const float* __restrict__ wout,
                                                  float* __restrict__ out) {
    __shared__ float As[32][Bn];
    __shared__ float Ws[32][On];
    int t = blockIdx.x;
    int tid = threadIdx.x;
    int ox = tid & 31, by = tid >> 5;
    int o0 = ox * 4, b0 = by * 8;
    unsigned long long acc[4][4] = {};

    const float* hsrc = g_h + (size_t)t * HB;
    for (int k0 = 0; k0 < Hn; k0 += 32) {
        const float4* asrc = (const float4*)(hsrc + (size_t)k0 * Bn);
        float4* adst = (float4*)&As[0][0];
        #pragma unroll
        for (int p = 0; p < 2; p++) adst[tid + p * 256] = asrc[tid + p * 256];
        #pragma unroll
        for (int p = 0; p < 4; p++) {
            int f = tid + p * 256;
            int k = f >> 5, c = f & 31;
            *(float4*)&Ws[k][c * 4] = *(const float4*)&wout[(size_t)(k0 + k) * On + c * 4];
        }
        __syncthreads();
        #pragma unroll 8
        for (int k = 0; k < 32; k++) {
            const unsigned long long* ap = (const unsigned long long*)&As[k][b0];
            unsigned long long a01 = ap[0], a23 = ap[1], a45 = ap[2], a67 = ap[3];
            float4 w = *(const float4*)&Ws[k][o0];
            unsigned long long w0 = splat2(w.x), w1 = splat2(w.y),
                               w2 = splat2(w.z), w3 = splat2(w.w);
            ffma2(acc[0][0], a01, w0); ffma2(acc[0][1], a01, w1);
            ffma2(acc[0][2], a01, w2); ffma2(acc[0][3], a01, w3);
            ffma2(acc[1][0], a23, w0); ffma2(acc[1][1], a23, w1);
            ffma2(acc[1][2], a23, w2); ffma2(acc[1][3], a23, w3);
            ffma2(acc[2][0], a45, w0); ffma2(acc[2][1], a45, w1);
            ffma2(acc[2][2], a45, w2); ffma2(acc[2][3], a45, w3);
            ffma2(acc[3][0], a67, w0); ffma2(acc[3][1], a67, w1);
            ffma2(acc[3][2], a67, w2); ffma2(acc[3][3], a67, w3);
        }
        __syncthreads();
    }
    #pragma unroll
    for (int bp = 0; bp < 4; bp++) {
        float2 u0 = unpack2(acc[bp][0]), u1 = unpack2(acc[bp][1]);
        float2 u2 = unpack2(acc[bp][2]), u3 = unpack2(acc[bp][3]);
        int b = b0 + bp * 2;
        *(float4*)&out[((size_t)b * Sn + t) * On + o0] = make_float4(u0.x, u1.x, u2.x, u3.x);
        *(float4*)&out[((size_t)(b + 1) * Sn + t) * On + o0] =
            make_float4(u0.y, u1.y, u2.y, u3.y);
    }
}

// ---------------------------------------------------------------------------
extern "C" void kernel_launch(void* const* d_in, const int* in_sizes, int n_in,
                              void* d_out, int out_size) {
    const float* x     = (const float*)d_in[0];
    const float* noise = (const float*)d_in[1];
    const float* wi    = (const float*)d_in[2];
    const float* wrec  = (const float*)d_in[3];
    const float* wout  = (const float*)d_in[4];
    const float* g     = (const float*)d_in[5];
    const float* h0    = (const float*)d_in[6];
    float* out = (float*)d_out;

    cudaFuncSetAttribute(loop_kernel, cudaFuncAttributeMaxDynamicSharedMemorySize,
                         SMEM_TOTAL);

    wprep_kernel<<<Hn * Hn / 256, 256>>>(wrec, g);
    u_kernel<<<dim3(Hn / 64, Sn - 1), 256>>>(x, noise, wi);
    hinit_kernel<<<HB / 256, 256>>>(h0);
    hbinit_kernel<<<HB / 256, 256>>>(h0);
    loop_kernel<<<NCTA, NTHR, SMEM_TOTAL>>>();
    out_kernel<<<Sn, 256>>>(wout, out);
}

// round 7
// speedup vs baseline: 2.0697x; 1.3140x over previous
#include <cuda_runtime.h>
#include <cuda_fp16.h>
#include <cstdint>
#include <cstddef>

// ---------------------------------------------------------------------------
// RNN_fish, persistent HMMA kernel, fp16 W-split (hi + 4096*lo), h as fp16.
//   h_t = 0.8*h_{t-1} + (g.h_{t-1}) @ (0.2*wrec^T) + U_t
// 2 mma chains: Whi*h + Wlo_scaled*h (separate fp32 acc, combined *2^-12).
// Effective: exact-W x fp16(h) -> per-step rel err ~2^-12, final ~3e-4.
// ---------------------------------------------------------------------------

namespace {
constexpr int Bn = 64;
constexpr int Sn = 512;
constexpr int In = 128;
constexpr int Hn = 2048;
constexpr int On = 128;
constexpr int KSPLIT = 8;
constexpr int KPER = Hn / KSPLIT;     // 256 k per CTA
constexpr int NCTA = 128;             // 16 j-tiles x 8 k-slices
constexpr int NTHR = 512;             // 16 warps
constexpr int HB = Hn * Bn;
constexpr float kNoise = 0.005f;
constexpr float kAlpha = 0.2f;
constexpr float kLoScale = 4096.0f;
constexpr float kLoInv = 1.0f / 4096.0f;

// smem layout (bytes). Rows padded to 528B -> conflict-free ldmatrix.
constexpr int ROWB = 528;
constexpr int OFF_WH = 0;                       // 128*528 = 67584
constexpr int OFF_WL = OFF_WH + 128 * ROWB;     // 67584
constexpr int OFF_BH = OFF_WL + 128 * ROWB;     // 135168 (64*528 = 33792)
constexpr int OFF_RED = OFF_BH;                 // pair-reduce stage, 8*1280*4 = 40960
constexpr int OFF_STG = OFF_RED + 40960;        // +16*66*4 = 4224
constexpr int SMEM_TOTAL = OFF_STG + 4224;      // 180416 (covers BH overlay too)
}

// device globals (allocation-free rule)
__device__ float g_h[(size_t)Sn * Hn * Bn];          // [t][j][b]
__device__ float g_U[(size_t)Sn * Hn * Bn];          // [t][j][b] (t>=1)
__device__ float g_part[(size_t)KSPLIT * Hn * Bn];   // [q][j][b]
__device__ __half g_Wh[(size_t)Hn * Hn];             // [j][k] fp16 hi of 0.2*g[k]*wrec[j][k]
__device__ __half g_Wl[(size_t)Hn * Hn];             // [j][k] fp16 4096*(v - hi)
__device__ __half g_hb[(size_t)Bn * Hn];             // [b][k] fp16 h_{t-1}
__device__ unsigned g_bar_count;
__device__ unsigned g_bar_gen;

// ---- helpers ----
__device__ __forceinline__ uint32_t smem_u32(const void* p) {
    uint32_t a;
    asm("{ .reg .u64 t; cvta.to.shared.u64 t, %1; cvt.u32.u64 %0, t; }" : "=r"(a) : "l"(p));
    return a;
}
__device__ __forceinline__ void ldsm4(uint32_t a[4], uint32_t addr) {
    asm volatile("ldmatrix.sync.aligned.m8n8.x4.shared.b16 {%0,%1,%2,%3}, [%4];"
                 : "=r"(a[0]), "=r"(a[1]), "=r"(a[2]), "=r"(a[3]) : "r"(addr));
}
__device__ __forceinline__ void mma16816(float c[4], const uint32_t a[4],
                                         uint32_t b0, uint32_t b1) {
    asm volatile("mma.sync.aligned.m16n8k16.row.col.f32.f16.f16.f32 "
                 "{%0,%1,%2,%3}, {%4,%5,%6,%7}, {%8,%9}, {%0,%1,%2,%3};"
                 : "+f"(c[0]), "+f"(c[1]), "+f"(c[2]), "+f"(c[3])
                 : "r"(a[0]), "r"(a[1]), "r"(a[2]), "r"(a[3]), "r"(b0), "r"(b1));
}
__device__ __forceinline__ void ffma2(unsigned long long &acc, unsigned long long a,
                                      unsigned long long b) {
    asm("fma.rn.f32x2 %0, %1, %2, %0;" : "+l"(acc) : "l"(a), "l"(b));
}
__device__ __forceinline__ unsigned long long splat2(float w) {
    unsigned long long r;
    asm("mov.b64 %0, {%1, %1};" : "=l"(r) : "f"(w));
    return r;
}
__device__ __forceinline__ float2 unpack2(unsigned long long v) {
    float2 r;
    asm("mov.b64 {%0, %1}, %2;" : "=f"(r.x), "=f"(r.y) : "l"(v));
    return r;
}

// software grid barrier (replay-deterministic)
__device__ __forceinline__ void grid_sync_dev() {
    __syncthreads();
    if (threadIdx.x == 0) {
        __threadfence();
        unsigned old, my;
        asm volatile("ld.acquire.gpu.global.u32 %0, [%1];"
                     : "=r"(old) : "l"(&g_bar_gen) : "memory");
        asm volatile("atom.release.gpu.global.add.u32 %0, [%1], %2;"
                     : "=r"(my) : "l"(&g_bar_count), "r"(1u) : "memory");
        if (my == (unsigned)(NCTA - 1)) {
            asm volatile("st.global.u32 [%0], %1;" :: "l"(&g_bar_count), "r"(0u) : "memory");
            asm volatile("red.release.gpu.global.add.u32 [%0], %1;"
                         :: "l"(&g_bar_gen), "r"(1u) : "memory");
        } else {
            unsigned cur;
            do {
                asm volatile("ld.acquire.gpu.global.u32 %0, [%1];"
                             : "=r"(cur) : "l"(&g_bar_gen) : "memory");
            } while (cur == old);
        }
        __threadfence();
    }
    __syncthreads();
}

// ---------------------------------------------------------------------------
// prep kernels
// ---------------------------------------------------------------------------
__global__ void wprep_kernel(const float* __restrict__ wrec, const float* __restrict__ g) {
    int n = blockIdx.x * blockDim.x + threadIdx.x;      // < Hn*Hn  ([j][k])
    int k = n & (Hn - 1);
    float v = kAlpha * g[k] * wrec[n];
    __half hi = __float2half_rn(v);
    g_Wh[n] = hi;
    g_Wl[n] = __float2half_rn((v - __half2float(hi)) * kLoScale);
}

__global__ void hinit_kernel(const float* __restrict__ h0) {
    int n = blockIdx.x * blockDim.x + threadIdx.x;      // < Hn*Bn, [j][b]
    g_h[n] = h0[n >> 6];
}

__global__ void hbinit_kernel(const float* __restrict__ h0) {
    int n = blockIdx.x * blockDim.x + threadIdx.x;      // < Bn*Hn, [b][k]
    g_hb[n] = __float2half_rn(h0[n & (Hn - 1)]);
}

// ---------------------------------------------------------------------------
// U[t][j][b] = alpha * x[b][t-1]@wi[:,j] + noise_std*noise[b][t-1][j]
// ---------------------------------------------------------------------------
__global__ __launch_bounds__(256) void u_kernel(const float* __restrict__ x,
                                                const float* __restrict__ noise,
                                                const float* __restrict__ wi) {
    __shared__ float As[64][66];
    __shared__ float Ws[64][64];
    int t = blockIdx.y + 1;
    int j0 = blockIdx.x * 64;
    int tid = threadIdx.x;
    int by = tid & 15, jx = tid >> 4;
    int b0 = by * 4;
    unsigned long long acc[4][2] = {};

    for (int i0 = 0; i0 < In; i0 += 64) {
        #pragma unroll
        for (int p = 0; p < 16; p++) {
            int f = tid + p * 256;
            int i = f & 63, b = f >> 6;
            As[i][b] = x[((size_t)b * Sn + (t - 1)) * In + i0 + i];
        }
        #pragma unroll
        for (int p = 0; p < 4; p++) {
            int f = tid + p * 256;
            int i = f >> 4, c = f & 15;
            *(float4*)&Ws[i][c * 4] = *(const float4*)&wi[(size_t)(i0 + i) * Hn + j0 + c * 4];
        }
        __syncthreads();
        #pragma unroll 16
        for (int k = 0; k < 64; k++) {
            const unsigned long long* ap = (const unsigned long long*)&As[k][b0];
            unsigned long long a01 = ap[0], a23 = ap[1];
            float4 w = *(const float4*)&Ws[k][jx * 4];
            unsigned long long w0 = splat2(w.x), w1 = splat2(w.y),
                               w2 = splat2(w.z), w3 = splat2(w.w);
            ffma2(acc[0][0], a01, w0); ffma2(acc[0][1], a23, w0);
            ffma2(acc[1][0], a01, w1); ffma2(acc[1][1], a23, w1);
            ffma2(acc[2][0], a01, w2); ffma2(acc[2][1], a23, w2);
            ffma2(acc[3][0], a01, w3); ffma2(acc[3][1], a23, w3);
        }
        __syncthreads();
    }
    #pragma unroll
    for (int jj = 0; jj < 4; jj++) {
        int j = j0 + jx * 4 + jj;
        float2 lo = unpack2(acc[jj][0]), hi = unpack2(acc[jj][1]);
        float4 v;
        v.x = kAlpha * lo.x + kNoise * noise[((size_t)(b0 + 0) * Sn + (t - 1)) * Hn + j];
        v.y = kAlpha * lo.y + kNoise * noise[((size_t)(b0 + 1) * Sn + (t - 1)) * Hn + j];
        v.z = kAlpha * hi.x + kNoise * noise[((size_t)(b0 + 2) * Sn + (t - 1)) * Hn + j];
        v.w = kAlpha * hi.y + kNoise * noise[((size_t)(b0 + 3) * Sn + (t - 1)) * Hn + j];
        *(float4*)&g_U[((size_t)t * Hn + j) * Bn + b0] = v;
    }
}

// ---------------------------------------------------------------------------
// persistent HMMA loop. CTA (jt,kq): partial D[128j x 64b] over its 256-k slice.
// 16 warps: tile = wid>>1, khalf = wid&1; warp tile 32j x 32b, K=128 per warp.
// 2 fp16 chains: Whi*h (acc1) + Wlo_scaled*h (acc2); combine acc1 + acc2/4096.
// pair (wid, wid^1) reduces k-halves via SMEM, writes g_part[kq].
// ---------------------------------------------------------------------------
__global__ __launch_bounds__(NTHR, 1) void loop_kernel() {
    extern __shared__ char smem[];
    const uint32_t sb = smem_u32(smem);
    const int tid = threadIdx.x;
    const int wid = tid >> 5, lane = tid & 31;
    const int cta = blockIdx.x;
    const int jt = cta >> 3, kq = cta & 7;
    const int j0 = jt * 128;
    const int kbase = kq * KPER;
    const int rc = cta * 16;               // phase-2 j-base

    const int tile = wid >> 1;             // 0..7
    const int khalf = wid & 1;
    const int mg = tile >> 1;              // 0..3 (32 j each)
    const int nh = tile & 1;               // 0..1 (32 b each)

    // ---- prologue: resident W hi/lo -> SMEM (padded rows) ----
    #pragma unroll
    for (int p = 0; p < 8; p++) {
        int f = tid + p * 512;             // < 4096
        int r = f >> 5, c = f & 31;
        size_t gi = (size_t)(j0 + r) * Hn + kbase + c * 8;
        *(uint4*)(smem + OFF_WH + r * ROWB + c * 16) = *(const uint4*)&g_Wh[gi];
        *(uint4*)(smem + OFF_WL + r * ROWB + c * 16) = *(const uint4*)&g_Wl[gi];
    }
    __syncthreads();

    // per-lane ldmatrix addresses (byte offsets within W/B blocks)
    const uint32_t aLane =
        (uint32_t)(mg * 32 + (lane & 15)) * ROWB + khalf * 256 + (lane >> 4) * 16;
    const uint32_t bLane =
        (uint32_t)(nh * 32 + (lane & 7) + ((lane >> 4) & 1) * 8) * ROWB +
        khalf * 256 + ((lane >> 3) & 1) * 16;
    const int g8 = lane >> 2, tg = lane & 3;
    float* red = (float*)(smem + OFF_RED) + tile * 1280;   // 32 rows x 40 floats
    float (*stage)[66] = (float (*)[66])(smem + OFF_STG);

    for (int t = 1; t < Sn; t++) {
        // ---- load B (fp16 h slice) ----
        #pragma unroll
        for (int p = 0; p < 4; p++) {
            int f = tid + p * 512;         // < 2048
            int b = f >> 5, c = f & 31;
            uint4 vh = __ldcg((const uint4*)&g_hb[(size_t)b * Hn + kbase + c * 8]);
            *(uint4*)(smem + OFF_BH + b * ROWB + c * 16) = vh;
        }
        __syncthreads();

        // ---- 2 mma chains, B fragments shared ----
        float acc1[2][4][4] = {}, acc2[2][4][4] = {};
        {
            const uint32_t aHi = sb + OFF_WH + aLane;
            const uint32_t aLo = sb + OFF_WL + aLane;
            const uint32_t bBase = sb + OFF_BH + bLane;
            #pragma unroll
            for (int kk = 0; kk < 8; kk++) {
                uint32_t Bv[4], Bw[4], A0[4], A1[4];
                ldsm4(Bv, bBase + kk * 32);
                ldsm4(Bw, bBase + kk * 32 + 16 * ROWB);
                ldsm4(A0, aHi + kk * 32);
                ldsm4(A1, aHi + kk * 32 + 16 * ROWB);
                mma16816(acc1[0][0], A0, Bv[0], Bv[1]);
                mma16816(acc1[0][1], A0, Bv[2], Bv[3]);
                mma16816(acc1[0][2], A0, Bw[0], Bw[1]);
                mma16816(acc1[0][3], A0, Bw[2], Bw[3]);
                mma16816(acc1[1][0], A1, Bv[0], Bv[1]);
                mma16816(acc1[1][1], A1, Bv[2], Bv[3]);
                mma16816(acc1[1][2], A1, Bw[0], Bw[1]);
                mma16816(acc1[1][3], A1, Bw[2], Bw[3]);
                ldsm4(A0, aLo + kk * 32);
                ldsm4(A1, aLo + kk * 32 + 16 * ROWB);
                mma16816(acc2[0][0], A0, Bv[0], Bv[1]);
                mma16816(acc2[0][1], A0, Bv[2], Bv[3]);
                mma16816(acc2[0][2], A0, Bw[0], Bw[1]);
                mma16816(acc2[0][3], A0, Bw[2], Bw[3]);
                mma16816(acc2[1][0], A1, Bv[0], Bv[1]);
                mma16816(acc2[1][1], A1, Bv[2], Bv[3]);
                mma16816(acc2[1][2], A1, Bw[0], Bw[1]);
                mma16816(acc2[1][3], A1, Bw[2], Bw[3]);
            }
        }
        // combine: acc1 += acc2 / 4096
        #pragma unroll
        for (int mt = 0; mt < 2; mt++)
            #pragma unroll
            for (int nt = 0; nt < 4; nt++)
                #pragma unroll
                for (int e = 0; e < 4; e++)
                    acc1[mt][nt][e] = fmaf(kLoInv, acc2[mt][nt][e], acc1[mt][nt][e]);

        __syncthreads();   // all warps done reading B (red overlays BH)

        // ---- pair-reduce k halves, write g_part ----
        if (khalf) {
            #pragma unroll
            for (int mt = 0; mt < 2; mt++)
                #pragma unroll
                for (int nt = 0; nt < 4; nt++) {
                    int r0 = mt * 16 + g8, cc = nt * 8 + tg * 2;
                    *(float2*)&red[r0 * 40 + cc] =
                        make_float2(acc1[mt][nt][0], acc1[mt][nt][1]);
                    *(float2*)&red[(r0 + 8) * 40 + cc] =
                        make_float2(acc1[mt][nt][2], acc1[mt][nt][3]);
                }
        }
        __syncthreads();
        if (!khalf) {
            #pragma unroll
            for (int mt = 0; mt < 2; mt++)
                #pragma unroll
                for (int nt = 0; nt < 4; nt++) {
                    int r0 = mt * 16 + g8, cc = nt * 8 + tg * 2;
                    float2 p0 = *(float2*)&red[r0 * 40 + cc];
                    float2 p1 = *(float2*)&red[(r0 + 8) * 40 + cc];
                    int j = j0 + mg * 32 + r0;
                    int bc = nh * 32 + cc;
                    __stcg((float2*)&g_part[((size_t)kq * Hn + j) * Bn + bc],
                           make_float2(acc1[mt][nt][0] + p0.x, acc1[mt][nt][1] + p0.y));
                    __stcg((float2*)&g_part[((size_t)kq * Hn + j + 8) * Bn + bc],
                           make_float2(acc1[mt][nt][2] + p1.x, acc1[mt][nt][3] + p1.y));
                }
        }

        grid_sync_dev();

        // ---- phase 2: reduce 8 k-slices + leak + U; CTA owns j in [rc, rc+16) ----
        {
            int e = tid * 2;
            int jl = e >> 6, bb = e & 63;
            size_t idx = (size_t)(rc + jl) * Bn + bb;
            float2 s = make_float2(0.f, 0.f);
            #pragma unroll
            for (int q = 0; q < KSPLIT; q++) {
                float2 v = __ldcg((const float2*)&g_part[(size_t)q * HB + idx]);
                s.x += v.x; s.y += v.y;
            }
            float2 hp = *(const float2*)&g_h[(size_t)(t - 1) * HB + idx];
            float2 uu = *(const float2*)&g_U[(size_t)t * HB + idx];
            float2 hn = make_float2((1.f - kAlpha) * hp.x + s.x + uu.x,
                                    (1.f - kAlpha) * hp.y + s.y + uu.y);
            *(float2*)&g_h[(size_t)t * HB + idx] = hn;
            *(float2*)&stage[jl][bb] = hn;
        }
        __syncthreads();
        {
            int b = tid >> 3, kk = tid & 7;
            __half2 hv;
            hv.x = __float2half_rn(stage[kk * 2][b]);
            hv.y = __float2half_rn(stage[kk * 2 + 1][b]);
            *(__half2*)&g_hb[(size_t)b * Hn + rc + kk * 2] = hv;
        }

        grid_sync_dev();
    }
}

// ---------------------------------------------------------------------------
// out[b][t][o] = sum_k g_h[t][k][b] * wout[k][o]
// ---------------------------------------------------------------------------
__global__ __launch_bounds__(256) void out_kernel(const float* __restrict__ wout,
                                                  float* __restrict__ out) {
    __shared__ float As[32][Bn];
    __shared__ float Ws[32][On];
    int t = blockIdx.x;
    int tid = threadIdx.x;
    int ox = tid & 31, by = tid >> 5;
    int o0 = ox * 4, b0 = by * 8;
    unsigned long long acc[4][4] = {};

    const float* hsrc = g_h + (size_t)t * HB;
    for (int k0 = 0; k0 < Hn; k0 += 32) {
        const float4* asrc = (const float4*)(hsrc + (size_t)k0 * Bn);
        float4* adst = (float4*)&As[0][0];
        #pragma unroll
        for (int p = 0; p < 2; p++) adst[tid + p * 256] = asrc[tid + p * 256];
        #pragma unroll
        for (int p = 0; p < 4; p++) {
            int f = tid + p * 256;
            int k = f >> 5, c = f & 31;
            *(float4*)&Ws[k][c * 4] = *(const float4*)&wout[(size_t)(k0 + k) * On + c * 4];
        }
        __syncthreads();
        #pragma unroll 8
        for (int k = 0; k < 32; k++) {
            const unsigned long long* ap = (const unsigned long long*)&As[k][b0];
            unsigned long long a01 = ap[0], a23 = ap[1], a45 = ap[2], a67 = ap[3];
            float4 w = *(const float4*)&Ws[k][o0];
            unsigned long long w0 = splat2(w.x), w1 = splat2(w.y),
                               w2 = splat2(w.z), w3 = splat2(w.w);
            ffma2(acc[0][0], a01, w0); ffma2(acc[0][1], a01, w1);
            ffma2(acc[0][2], a01, w2); ffma2(acc[0][3], a01, w3);
            ffma2(acc[1][0], a23, w0); ffma2(acc[1][1], a23, w1);
            ffma2(acc[1][2], a23, w2); ffma2(acc[1][3], a23, w3);
            ffma2(acc[2][0], a45, w0); ffma2(acc[2][1], a45, w1);
            ffma2(acc[2][2], a45, w2); ffma2(acc[2][3], a45, w3);
            ffma2(acc[3][0], a67, w0); ffma2(acc[3][1], a67, w1);
            ffma2(acc[3][2], a67, w2); ffma2(acc[3][3], a67, w3);
        }
        __syncthreads();
    }
    #pragma unroll
    for (int bp = 0; bp < 4; bp++) {
        float2 u0 = unpack2(acc[bp][0]), u1 = unpack2(acc[bp][1]);
        float2 u2 = unpack2(acc[bp][2]), u3 = unpack2(acc[bp][3]);
        int b = b0 + bp * 2;
        *(float4*)&out[((size_t)b * Sn + t) * On + o0] = make_float4(u0.x, u1.x, u2.x, u3.x);
        *(float4*)&out[((size_t)(b + 1) * Sn + t) * On + o0] =
            make_float4(u0.y, u1.y, u2.y, u3.y);
    }
}

// ---------------------------------------------------------------------------
extern "C" void kernel_launch(void* const* d_in, const int* in_sizes, int n_in,
                              void* d_out, int out_size) {
    const float* x     = (const float*)d_in[0];
    const float* noise = (const float*)d_in[1];
    const float* wi    = (const float*)d_in[2];
    const float* wrec  = (const float*)d_in[3];
    const float* wout  = (const float*)d_in[4];
    const float* g     = (const float*)d_in[5];
    const float* h0    = (const float*)d_in[6];
    float* out = (float*)d_out;

    cudaFuncSetAttribute(loop_kernel, cudaFuncAttributeMaxDynamicSharedMemorySize,
                         SMEM_TOTAL);

    wprep_kernel<<<Hn * Hn / 256, 256>>>(wrec, g);
    u_kernel<<<dim3(Hn / 64, Sn - 1), 256>>>(x, noise, wi);
    hinit_kernel<<<HB / 256, 256>>>(h0);
    hbinit_kernel<<<HB / 256, 256>>>(h0);
    loop_kernel<<<NCTA, NTHR, SMEM_TOTAL>>>();
    out_kernel<<<Sn, 256>>>(wout, out);
}

// round 8
// speedup vs baseline: 2.3145x; 1.1183x over previous
#include <cuda_runtime.h>
#include <cuda_fp16.h>
#include <cstdint>
#include <cstddef>

// ---------------------------------------------------------------------------
// RNN_fish, persistent HMMA kernel, single fp16 chain:
//   h_t = 0.8*h_{t-1} + (g.h_{t-1}) @ (0.2*wrec^T) + U_t
// W' = fp16(0.2*g[k]*wrec[j][k]); h carried fp32, fed to MMA as fp16.
// 144 CTAs = 16 j-tiles x 9 uneven k-slices (14 or 15 k16-units each).
// ---------------------------------------------------------------------------

namespace {
constexpr int Bn = 64;
constexpr int Sn = 512;
constexpr int In = 128;
constexpr int Hn = 2048;
constexpr int On = 128;
constexpr int KSPLIT = 9;
constexpr int NCTA = 144;             // 16 j-tiles x 9 k-slices
constexpr int NTHR = 512;             // 16 warps
constexpr int HB = Hn * Bn;
constexpr float kNoise = 0.005f;
constexpr float kAlpha = 0.2f;

// k16-units per slice: slices 0,1 get 15, slices 2..8 get 14 (2*15+7*14=128)
__host__ __device__ __forceinline__ int slice_units(int kq) { return 14 + (kq < 2); }
__host__ __device__ __forceinline__ int slice_start16(int kq) {
    return kq * 14 + (kq < 2 ? kq : 2);
}

// smem layout (bytes). Rows padded to 528B -> conflict-free ldmatrix.
constexpr int ROWB = 528;
constexpr int OFF_WH = 0;                       // 128*528 = 67584
constexpr int OFF_BH = OFF_WH + 128 * ROWB;     // 67584 (+64*528 = 33792)
constexpr int OFF_RED = OFF_BH;                 // pair-reduce stage overlay, 40960
constexpr int OFF_STG = OFF_RED + 40960;        // +16*66*4 = 4224
constexpr int SMEM_TOTAL = OFF_STG + 4224;      // 112768
}

// device globals (allocation-free rule)
__device__ float g_h[(size_t)Sn * Hn * Bn];          // [t][j][b]
__device__ float g_U[(size_t)Sn * Hn * Bn];          // [t][j][b] (t>=1)
__device__ float g_part[(size_t)KSPLIT * Hn * Bn];   // [q][j][b]
__device__ __half g_Wh[(size_t)Hn * Hn];             // [j][k] fp16 of 0.2*g[k]*wrec[j][k]
__device__ __half g_hb[(size_t)Bn * Hn];             // [b][k] fp16 h_{t-1}
__device__ unsigned g_bar_count;
__device__ unsigned g_bar_gen;

// ---- helpers ----
__device__ __forceinline__ uint32_t smem_u32(const void* p) {
    uint32_t a;
    asm("{ .reg .u64 t; cvta.to.shared.u64 t, %1; cvt.u32.u64 %0, t; }" : "=r"(a) : "l"(p));
    return a;
}
__device__ __forceinline__ void ldsm4(uint32_t a[4], uint32_t addr) {
    asm volatile("ldmatrix.sync.aligned.m8n8.x4.shared.b16 {%0,%1,%2,%3}, [%4];"
                 : "=r"(a[0]), "=r"(a[1]), "=r"(a[2]), "=r"(a[3]) : "r"(addr));
}
__device__ __forceinline__ void mma16816(float c[4], const uint32_t a[4],
                                         uint32_t b0, uint32_t b1) {
    asm volatile("mma.sync.aligned.m16n8k16.row.col.f32.f16.f16.f32 "
                 "{%0,%1,%2,%3}, {%4,%5,%6,%7}, {%8,%9}, {%0,%1,%2,%3};"
                 : "+f"(c[0]), "+f"(c[1]), "+f"(c[2]), "+f"(c[3])
                 : "r"(a[0]), "r"(a[1]), "r"(a[2]), "r"(a[3]), "r"(b0), "r"(b1));
}
__device__ __forceinline__ void ffma2(unsigned long long &acc, unsigned long long a,
                                      unsigned long long b) {
    asm("fma.rn.f32x2 %0, %1, %2, %0;" : "+l"(acc) : "l"(a), "l"(b));
}
__device__ __forceinline__ unsigned long long splat2(float w) {
    unsigned long long r;
    asm("mov.b64 %0, {%1, %1};" : "=l"(r) : "f"(w));
    return r;
}
__device__ __forceinline__ float2 unpack2(unsigned long long v) {
    float2 r;
    asm("mov.b64 {%0, %1}, %2;" : "=f"(r.x), "=f"(r.y) : "l"(v));
    return r;
}

// software grid barrier (replay-deterministic) -- proven, unchanged
__device__ __forceinline__ void grid_sync_dev() {
    __syncthreads();
    if (threadIdx.x == 0) {
        __threadfence();
        unsigned old, my;
        asm volatile("ld.acquire.gpu.global.u32 %0, [%1];"
                     : "=r"(old) : "l"(&g_bar_gen) : "memory");
        asm volatile("atom.release.gpu.global.add.u32 %0, [%1], %2;"
                     : "=r"(my) : "l"(&g_bar_count), "r"(1u) : "memory");
        if (my == (unsigned)(NCTA - 1)) {
            asm volatile("st.global.u32 [%0], %1;" :: "l"(&g_bar_count), "r"(0u) : "memory");
            asm volatile("red.release.gpu.global.add.u32 [%0], %1;"
                         :: "l"(&g_bar_gen), "r"(1u) : "memory");
        } else {
            unsigned cur;
            do {
                asm volatile("ld.acquire.gpu.global.u32 %0, [%1];"
                             : "=r"(cur) : "l"(&g_bar_gen) : "memory");
            } while (cur == old);
        }
        __threadfence();
    }
    __syncthreads();
}

// ---------------------------------------------------------------------------
// prep kernels
// ---------------------------------------------------------------------------
__global__ void wprep_kernel(const float* __restrict__ wrec, const float* __restrict__ g) {
    int n = blockIdx.x * blockDim.x + threadIdx.x;      // < Hn*Hn  ([j][k])
    int k = n & (Hn - 1);
    g_Wh[n] = __float2half_rn(kAlpha * g[k] * wrec[n]);
}

__global__ void hinit_kernel(const float* __restrict__ h0) {
    int n = blockIdx.x * blockDim.x + threadIdx.x;      // < Hn*Bn, [j][b]
    g_h[n] = h0[n >> 6];
}

__global__ void hbinit_kernel(const float* __restrict__ h0) {
    int n = blockIdx.x * blockDim.x + threadIdx.x;      // < Bn*Hn, [b][k]
    g_hb[n] = __float2half_rn(h0[n & (Hn - 1)]);
}

// ---------------------------------------------------------------------------
// U[t][j][b] = alpha * x[b][t-1]@wi[:,j] + noise_std*noise[b][t-1][j]
// ---------------------------------------------------------------------------
__global__ __launch_bounds__(256) void u_kernel(const float* __restrict__ x,
                                                const float* __restrict__ noise,
                                                const float* __restrict__ wi) {
    __shared__ float As[64][66];
    __shared__ float Ws[64][64];
    int t = blockIdx.y + 1;
    int j0 = blockIdx.x * 64;
    int tid = threadIdx.x;
    int by = tid & 15, jx = tid >> 4;
    int b0 = by * 4;
    unsigned long long acc[4][2] = {};

    for (int i0 = 0; i0 < In; i0 += 64) {
        #pragma unroll
        for (int p = 0; p < 16; p++) {
            int f = tid + p * 256;
            int i = f & 63, b = f >> 6;
            As[i][b] = x[((size_t)b * Sn + (t - 1)) * In + i0 + i];
        }
        #pragma unroll
        for (int p = 0; p < 4; p++) {
            int f = tid + p * 256;
            int i = f >> 4, c = f & 15;
            *(float4*)&Ws[i][c * 4] = *(const float4*)&wi[(size_t)(i0 + i) * Hn + j0 + c * 4];
        }
        __syncthreads();
        #pragma unroll 16
        for (int k = 0; k < 64; k++) {
            const unsigned long long* ap = (const unsigned long long*)&As[k][b0];
            unsigned long long a01 = ap[0], a23 = ap[1];
            float4 w = *(const float4*)&Ws[k][jx * 4];
            unsigned long long w0 = splat2(w.x), w1 = splat2(w.y),
                               w2 = splat2(w.z), w3 = splat2(w.w);
            ffma2(acc[0][0], a01, w0); ffma2(acc[0][1], a23, w0);
            ffma2(acc[1][0], a01, w1); ffma2(acc[1][1], a23, w1);
            ffma2(acc[2][0], a01, w2); ffma2(acc[2][1], a23, w2);
            ffma2(acc[3][0], a01, w3); ffma2(acc[3][1], a23, w3);
        }
        __syncthreads();
    }
    #pragma unroll
    for (int jj = 0; jj < 4; jj++) {
        int j = j0 + jx * 4 + jj;
        float2 lo = unpack2(acc[jj][0]), hi = unpack2(acc[jj][1]);
        float4 v;
        v.x = kAlpha * lo.x + kNoise * noise[((size_t)(b0 + 0) * Sn + (t - 1)) * Hn + j];
        v.y = kAlpha * lo.y + kNoise * noise[((size_t)(b0 + 1) * Sn + (t - 1)) * Hn + j];
        v.z = kAlpha * hi.x + kNoise * noise[((size_t)(b0 + 2) * Sn + (t - 1)) * Hn + j];
        v.w = kAlpha * hi.y + kNoise * noise[((size_t)(b0 + 3) * Sn + (t - 1)) * Hn + j];
        *(float4*)&g_U[((size_t)t * Hn + j) * Bn + b0] = v;
    }
}

// ---------------------------------------------------------------------------
// persistent HMMA loop. CTA (jt,kq): partial D[128j x 64b] over its k-slice
// (14 or 15 k16-units). 16 warps: tile = wid>>1, khalf = wid&1.
// Warp tile 32j x 32b; khalf0 takes ceil(units/2), khalf1 the rest.
// Single fp16 chain; pair (wid, wid^1) reduces k-halves via SMEM -> g_part.
// ---------------------------------------------------------------------------
__global__ __launch_bounds__(NTHR, 1) void loop_kernel() {
    extern __shared__ char smem[];
    const uint32_t sb = smem_u32(smem);
    const int tid = threadIdx.x;
    const int wid = tid >> 5, lane = tid & 31;
    const int cta = blockIdx.x;
    const int jt = cta / KSPLIT, kq = cta % KSPLIT;
    const int j0 = jt * 128;
    const int ku = slice_units(kq);           // 14 or 15
    const int ku2 = ku * 2;                   // 16B chunks per row
    const int kbase = slice_start16(kq) * 16; // element base
    const int u0 = (ku + 1) >> 1;             // khalf0 units (7 or 8)
    const int rc = cta * 16;                  // phase-2 j-base (cta < 128 only)

    const int tile = wid >> 1;                // 0..7
    const int khalf = wid & 1;
    const int mg = tile >> 1;                 // 0..3 (32 j each)
    const int nh = tile & 1;                  // 0..1 (32 b each)
    const int myU = khalf ? (ku - u0) : u0;   // k16-units for this warp
    const uint32_t koff = (uint32_t)(khalf ? u0 * 32 : 0);

    // ---- prologue: resident W -> SMEM (padded rows) ----
    for (int p = 0; p < 8; p++) {
        int f = tid + p * 512;                // < 4096
        int r = f >> 5, c = f & 31;
        if (c < ku2)
            *(uint4*)(smem + OFF_WH + r * ROWB + c * 16) =
                *(const uint4*)&g_Wh[(size_t)(j0 + r) * Hn + kbase + c * 8];
    }
    __syncthreads();

    // per-lane ldmatrix addresses (byte offsets within W/B blocks)
    const uint32_t aLane =
        (uint32_t)(mg * 32 + (lane & 15)) * ROWB + koff + (lane >> 4) * 16;
    const uint32_t bLane =
        (uint32_t)(nh * 32 + (lane & 7) + ((lane >> 4) & 1) * 8) * ROWB +
        koff + ((lane >> 3) & 1) * 16;
    const int g8 = lane >> 2, tg = lane & 3;
    float* red = (float*)(smem + OFF_RED) + tile * 1280;   // 32 rows x 40 floats
    float (*stage)[66] = (float (*)[66])(smem + OFF_STG);

    for (int t = 1; t < Sn; t++) {
        // ---- load B (fp16 h slice) ----
        #pragma unroll
        for (int p = 0; p < 4; p++) {
            int f = tid + p * 512;            // < 2048
            int b = f >> 5, c = f & 31;
            if (c < ku2)
                *(uint4*)(smem + OFF_BH + b * ROWB + c * 16) =
                    __ldcg((const uint4*)&g_hb[(size_t)b * Hn + kbase + c * 8]);
        }
        __syncthreads();

        // ---- single mma chain ----
        float acc1[2][4][4] = {};
        {
            const uint32_t aHi = sb + OFF_WH + aLane;
            const uint32_t bBase = sb + OFF_BH + bLane;
            #pragma unroll 4
            for (int kk = 0; kk < myU; kk++) {
                uint32_t Bv[4], Bw[4], A0[4], A1[4];
                ldsm4(Bv, bBase + kk * 32);
                ldsm4(Bw, bBase + kk * 32 + 16 * ROWB);
                ldsm4(A0, aHi + kk * 32);
                ldsm4(A1, aHi + kk * 32 + 16 * ROWB);
                mma16816(acc1[0][0], A0, Bv[0], Bv[1]);
                mma16816(acc1[0][1], A0, Bv[2], Bv[3]);
                mma16816(acc1[0][2], A0, Bw[0], Bw[1]);
                mma16816(acc1[0][3], A0, Bw[2], Bw[3]);
                mma16816(acc1[1][0], A1, Bv[0], Bv[1]);
                mma16816(acc1[1][1], A1, Bv[2], Bv[3]);
                mma16816(acc1[1][2], A1, Bw[0], Bw[1]);
                mma16816(acc1[1][3], A1, Bw[2], Bw[3]);
            }
        }
        __syncthreads();   // all warps done reading B (red overlays BH)

        // ---- pair-reduce k halves, write g_part ----
        if (khalf) {
            #pragma unroll
            for (int mt = 0; mt < 2; mt++)
                #pragma unroll
                for (int nt = 0; nt < 4; nt++) {
                    int r0 = mt * 16 + g8, cc = nt * 8 + tg * 2;
                    *(float2*)&red[r0 * 40 + cc] =
                        make_float2(acc1[mt][nt][0], acc1[mt][nt][1]);
                    *(float2*)&red[(r0 + 8) * 40 + cc] =
                        make_float2(acc1[mt][nt][2], acc1[mt][nt][3]);
                }
        }
        __syncthreads();
        if (!khalf) {
            #pragma unroll
            for (int mt = 0; mt < 2; mt++)
                #pragma unroll
                for (int nt = 0; nt < 4; nt++) {
                    int r0 = mt * 16 + g8, cc = nt * 8 + tg * 2;
                    float2 p0 = *(float2*)&red[r0 * 40 + cc];
                    float2 p1 = *(float2*)&red[(r0 + 8) * 40 + cc];
                    int j = j0 + mg * 32 + r0;
                    int bc = nh * 32 + cc;
                    __stcg((float2*)&g_part[((size_t)kq * Hn + j) * Bn + bc],
                           make_float2(acc1[mt][nt][0] + p0.x, acc1[mt][nt][1] + p0.y));
                    __stcg((float2*)&g_part[((size_t)kq * Hn + j + 8) * Bn + bc],
                           make_float2(acc1[mt][nt][2] + p1.x, acc1[mt][nt][3] + p1.y));
                }
        }

        // ---- prefetch phase-2 operands (barrier-independent) ----
        float2 hp = make_float2(0.f, 0.f), uu = make_float2(0.f, 0.f);
        int jl = 0, bb = 0;
        size_t idx = 0;
        if (cta < 128) {
            int e = tid * 2;
            jl = e >> 6; bb = e & 63;
            idx = (size_t)(rc + jl) * Bn + bb;
            hp = *(const float2*)&g_h[(size_t)(t - 1) * HB + idx];
            uu = *(const float2*)&g_U[(size_t)t * HB + idx];
        }

        grid_sync_dev();

        // ---- phase 2: reduce 9 k-slices + leak + U; CTAs 0..127 own 16 j each ----
        if (cta < 128) {
            float2 s = make_float2(0.f, 0.f);
            #pragma unroll
            for (int q = 0; q < KSPLIT; q++) {
                float2 v = __ldcg((const float2*)&g_part[(size_t)q * HB + idx]);
                s.x += v.x; s.y += v.y;
            }
            float2 hn = make_float2((1.f - kAlpha) * hp.x + s.x + uu.x,
                                    (1.f - kAlpha) * hp.y + s.y + uu.y);
            *(float2*)&g_h[(size_t)t * HB + idx] = hn;
            *(float2*)&stage[jl][bb] = hn;
            __syncthreads();
            int b = tid >> 3, kk = tid & 7;
            __half2 hv;
            hv.x = __float2half_rn(stage[kk * 2][b]);
            hv.y = __float2half_rn(stage[kk * 2 + 1][b]);
            *(__half2*)&g_hb[(size_t)b * Hn + rc + kk * 2] = hv;
        }

        grid_sync_dev();
    }
}

// ---------------------------------------------------------------------------
// out[b][t][o] = sum_k g_h[t][k][b] * wout[k][o]
// ---------------------------------------------------------------------------
__global__ __launch_bounds__(256) void out_kernel(const float* __restrict__ wout,
                                                  float* __restrict__ out) {
    __shared__ float As[32][Bn];
    __shared__ float Ws[32][On];
    int t = blockIdx.x;
    int tid = threadIdx.x;
    int ox = tid & 31, by = tid >> 5;
    int o0 = ox * 4, b0 = by * 8;
    unsigned long long acc[4][4] = {};

    const float* hsrc = g_h + (size_t)t * HB;
    for (int k0 = 0; k0 < Hn; k0 += 32) {
        const float4* asrc = (const float4*)(hsrc + (size_t)k0 * Bn);
        float4* adst = (float4*)&As[0][0];
        #pragma unroll
        for (int p = 0; p < 2; p++) adst[tid + p * 256] = asrc[tid + p * 256];
        #pragma unroll
        for (int p = 0; p < 4; p++) {
            int f = tid + p * 256;
            int k = f >> 5, c = f & 31;
            *(float4*)&Ws[k][c * 4] = *(const float4*)&wout[(size_t)(k0 + k) * On + c * 4];
        }
        __syncthreads();
        #pragma unroll 8
        for (int k = 0; k < 32; k++) {
            const unsigned long long* ap = (const unsigned long long*)&As[k][b0];
            unsigned long long a01 = ap[0], a23 = ap[1], a45 = ap[2], a67 = ap[3];
            float4 w = *(const float4*)&Ws[k][o0];
            unsigned long long w0 = splat2(w.x), w1 = splat2(w.y),
                               w2 = splat2(w.z), w3 = splat2(w.w);
            ffma2(acc[0][0], a01, w0); ffma2(acc[0][1], a01, w1);
            ffma2(acc[0][2], a01, w2); ffma2(acc[0][3], a01, w3);
            ffma2(acc[1][0], a23, w0); ffma2(acc[1][1], a23, w1);
            ffma2(acc[1][2], a23, w2); ffma2(acc[1][3], a23, w3);
            ffma2(acc[2][0], a45, w0); ffma2(acc[2][1], a45, w1);
            ffma2(acc[2][2], a45, w2); ffma2(acc[2][3], a45, w3);
            ffma2(acc[3][0], a67, w0); ffma2(acc[3][1], a67, w1);
            ffma2(acc[3][2], a67, w2); ffma2(acc[3][3], a67, w3);
        }
        __syncthreads();
    }
    #pragma unroll
    for (int bp = 0; bp < 4; bp++) {
        float2 u0 = unpack2(acc[bp][0]), u1 = unpack2(acc[bp][1]);
        float2 u2 = unpack2(acc[bp][2]), u3 = unpack2(acc[bp][3]);
        int b = b0 + bp * 2;
        *(float4*)&out[((size_t)b * Sn + t) * On + o0] = make_float4(u0.x, u1.x, u2.x, u3.x);
        *(float4*)&out[((size_t)(b + 1) * Sn + t) * On + o0] =
            make_float4(u0.y, u1.y, u2.y, u3.y);
    }
}

// ---------------------------------------------------------------------------
extern "C" void kernel_launch(void* const* d_in, const int* in_sizes, int n_in,
                              void* d_out, int out_size) {
    const float* x     = (const float*)d_in[0];
    const float* noise = (const float*)d_in[1];
    const float* wi    = (const float*)d_in[2];
    const float* wrec  = (const float*)d_in[3];
    const float* wout  = (const float*)d_in[4];
    const float* g     = (const float*)d_in[5];
    const float* h0    = (const float*)d_in[6];
    float* out = (float*)d_out;

    cudaFuncSetAttribute(loop_kernel, cudaFuncAttributeMaxDynamicSharedMemorySize,
                         SMEM_TOTAL);

    wprep_kernel<<<Hn * Hn / 256, 256>>>(wrec, g);
    u_kernel<<<dim3(Hn / 64, Sn - 1), 256>>>(x, noise, wi);
    hinit_kernel<<<HB / 256, 256>>>(h0);
    hbinit_kernel<<<HB / 256, 256>>>(h0);
    loop_kernel<<<NCTA, NTHR, SMEM_TOTAL>>>();
    out_kernel<<<Sn, 256>>>(wout, out);
}